// round 16
// baseline (speedup 1.0000x reference)
#include <cuda_runtime.h>
#include <cuda_fp16.h>
#include <cstdint>

#define E_      8
#define D_      512
#define TMAX    32768
#define MAXTILES 264

// ---------------- scratch (allocation-free __device__ globals) ----------------
__device__ int g_cursor[E_];
__device__ int g_bucket[E_ * TMAX];

// per-expert padded gathered rows: row (e, pos) at g_Xg[(e*TMAX+pos)*D_]
__device__ __align__(16) __half g_Xg[(size_t)E_ * TMAX * D_];
__device__ __align__(16) __half g_Wh[(size_t)E_ * D_ * D_];

// ---------------- helpers ----------------
__device__ __forceinline__ uint32_t smem_u32(const void* p) {
    uint32_t a;
    asm("{ .reg .u64 t; cvta.to.shared.u64 t, %1; cvt.u32.u64 %0, t; }" : "=r"(a) : "l"(p));
    return a;
}

#define CP16(d, s) asm volatile("cp.async.cg.shared.global [%0], [%1], 16;" :: "r"(d), "l"(s) : "memory")

#define LDSM4(r, a)                                                                  \
    asm volatile("ldmatrix.sync.aligned.m8n8.x4.shared.b16 {%0,%1,%2,%3}, [%4];"     \
        : "=r"((r)[0]), "=r"((r)[1]), "=r"((r)[2]), "=r"((r)[3]) : "r"(a))

#define MMA(c, a, b)                                                                 \
    asm volatile("mma.sync.aligned.m16n8k16.row.col.f32.f16.f16.f32 "                \
        "{%0,%1,%2,%3},{%4,%5,%6,%7},{%8,%9},{%0,%1,%2,%3};"                         \
        : "+f"((c)[0]), "+f"((c)[1]), "+f"((c)[2]), "+f"((c)[3])                     \
        : "r"((a)[0]), "r"((a)[1]), "r"((a)[2]), "r"((a)[3]),                        \
          "r"((b)[0]), "r"((b)[1]))

// ---------------- zero cursors ----------------
__global__ void k_zero() {
    if (threadIdx.x < E_) g_cursor[threadIdx.x] = 0;
}

// ---------------- fused prep: scatter+copy (blocks 0..127) + W conv ----------------
// Scatter blocks: 256 tokens each; after positions are known, 512 threads
// cooperatively copy+convert each token row into its per-expert slot.
#define SCAT_BLK 128
#define TOK_PER_BLK 256
__global__ void __launch_bounds__(512)
k_prep2(const int* __restrict__ p, int T,
        const float* __restrict__ x, const float* __restrict__ W) {
    const int tid = threadIdx.x;
    if (blockIdx.x < SCAT_BLK) {
        __shared__ int s_cnt[E_], s_base[E_];
        __shared__ int s_dst[TOK_PER_BLK];
        __shared__ int s_tok[TOK_PER_BLK];
        if (tid < E_) s_cnt[tid] = 0;
        __syncthreads();
        int e = 0, rank = 0, t = 0;
        if (tid < TOK_PER_BLK) {
            t = blockIdx.x * TOK_PER_BLK + tid;
            e = p[t];
            rank = atomicAdd(&s_cnt[e], 1);
        }
        __syncthreads();
        if (tid < E_ && s_cnt[tid])
            s_base[tid] = atomicAdd(&g_cursor[tid], s_cnt[tid]);
        __syncthreads();
        if (tid < TOK_PER_BLK) {
            int pos = s_base[e] + rank;
            g_bucket[e * TMAX + pos] = t;
            s_tok[tid] = t;
            s_dst[tid] = e * TMAX + pos;
        }
        __syncthreads();
        // cooperative row copy: one row per iteration, tid = column
        #pragma unroll 4
        for (int i = 0; i < TOK_PER_BLK; i++) {
            const int tok = s_tok[i];
            const int dst = s_dst[i];
            float v = x[(size_t)tok * D_ + tid];
            g_Xg[(size_t)dst * D_ + tid] = __float2half_rn(v);
        }
    } else {
        size_t i = (size_t)(blockIdx.x - SCAT_BLK) * 512 + tid;   // per 8 floats
        float4 v0 = ((const float4*)W)[2 * i];
        float4 v1 = ((const float4*)W)[2 * i + 1];
        __half2 h0 = __floats2half2_rn(v0.x, v0.y);
        __half2 h1 = __floats2half2_rn(v0.z, v0.w);
        __half2 h2 = __floats2half2_rn(v1.x, v1.y);
        __half2 h3 = __floats2half2_rn(v1.z, v1.w);
        uint4 o;
        o.x = *(uint32_t*)&h0; o.y = *(uint32_t*)&h1;
        o.z = *(uint32_t*)&h2; o.w = *(uint32_t*)&h3;
        ((uint4*)g_Wh)[i] = o;
    }
}

// ---------------- grouped GEMM: FP16 HMMA, K-slab 64, 3-stage (r13) ----------------
// CTA 128(M) x 128(N), 8 warps, warp tile 32x64. K=512 in 8 slabs of 64.
// Stage = 2 sub-chunks of 32: [A0 A1 | W0 W1], each sub 128 rows x 64B,
// XOR swizzle c' = c ^ ((row>>1)&3).
#define OFF_A       0
#define OFF_W       16384
#define SUB         8192
#define STG         32768
#define NST         3
#define SMEM_GEMM   (1024 + NST * STG)

__global__ void __launch_bounds__(256, 2)
k_gemm(const float* __restrict__ bias, float* __restrict__ out) {
    extern __shared__ unsigned char smem[];
    const int tid = threadIdx.x, lane = tid & 31, wid = tid >> 5;

    // ---- inline tile list ----
    int* rows = (int*)smem;
    __shared__ int s_e, s_m, s_cnt;
    if (tid == 0) {
        int ti = blockIdx.y;
        int ee = -1, mm = 0, cc = 0;
        #pragma unroll
        for (int k = 0; k < E_; k++) {
            int c = g_cursor[k];
            int mt = (c + 127) >> 7;
            if (ee < 0) {
                if (ti < mt) { ee = k; mm = ti; cc = c; }
                else ti -= mt;
            }
        }
        s_e = ee; s_m = mm; s_cnt = cc;
    }
    __syncthreads();
    const int e = s_e;
    if (e < 0) return;
    const int nt = blockIdx.x, mtile = s_m, count = s_cnt;

    if (tid < 128) {
        int m = mtile * 128 + tid;
        rows[tid] = (m < count) ? g_bucket[e * TMAX + m] : -1;
    }
    __syncthreads();

    // ---- loader: row = tid>>1, 32B half = tid&1; A per-expert padded ----
    const int lrow = tid >> 1;
    const int hh = tid & 1;
    const int am = mtile * 128 + lrow;
    const int arow = e * TMAX + ((am < count) ? am : 0);
    const char* srcA = (const char*)(g_Xg + (size_t)arow * D_) + hh * 32;
    const char* srcW = (const char*)(g_Wh + ((size_t)e * D_ + (size_t)(nt * 128 + lrow)) * D_)
                       + hh * 32;

    const uint32_t sb = smem_u32(smem) + 1024;
    const uint32_t c0 = (uint32_t)hh * 2;
    const uint32_t sw_ = (uint32_t)((lrow >> 1) & 3);
    const uint32_t d0 = (uint32_t)lrow * 64 + ((c0 ^ sw_) * 16);
    const uint32_t d1 = (uint32_t)lrow * 64 + (((c0 + 1) ^ sw_) * 16);

    #define LOAD_STAGE(st, kc2) do {                                                 \
        uint32_t b_ = sb + (uint32_t)(st) * STG;                                      \
        const char* sa_ = srcA + (size_t)(kc2) * 128;                                 \
        const char* sw2_ = srcW + (size_t)(kc2) * 128;                                \
        CP16(b_ + OFF_A + d0,       sa_);       CP16(b_ + OFF_A + d1,       sa_ + 16);\
        CP16(b_ + OFF_A + SUB + d0, sa_ + 64);  CP16(b_ + OFF_A + SUB + d1, sa_ + 80);\
        CP16(b_ + OFF_W + d0,       sw2_);      CP16(b_ + OFF_W + d1,       sw2_ + 16);\
        CP16(b_ + OFF_W + SUB + d0, sw2_ + 64); CP16(b_ + OFF_W + SUB + d1, sw2_ + 80);\
        asm volatile("cp.async.commit_group;" ::: "memory");                          \
    } while (0)

    // ---- mma fragment addressing: warp tile 32x64 ----
    const int m0 = (wid & 3) * 32;
    const int n0 = (wid >> 2) * 64;
    const uint32_t rA  = (uint32_t)(m0 + (lane & 15));
    const uint32_t hA  = (uint32_t)((lane >> 4) & 1);
    const uint32_t sA  = (rA >> 1) & 3;
    const uint32_t rowA = rA * 64;
    const uint32_t rB0 = (uint32_t)(n0 + ((lane >> 4) & 1) * 8 + (lane & 7));
    const uint32_t hB  = (uint32_t)((lane >> 3) & 1);
    const uint32_t sB  = (rB0 >> 1) & 3;
    const uint32_t rowB = rB0 * 64;

    float acc[2][8][4];
    #pragma unroll
    for (int i = 0; i < 2; i++)
        #pragma unroll
        for (int j = 0; j < 8; j++)
            #pragma unroll
            for (int q = 0; q < 4; q++) acc[i][j][q] = 0.f;

    LOAD_STAGE(0, 0);
    LOAD_STAGE(1, 1);

    for (int kc2 = 0; kc2 < 8; kc2++) {
        if (kc2 < 6) asm volatile("cp.async.wait_group 1;" ::: "memory");
        else         asm volatile("cp.async.wait_group 0;" ::: "memory");
        __syncthreads();
        if (kc2 + 2 < 8) {
            int st = (kc2 + 2) % 3;
            LOAD_STAGE(st, kc2 + 2);
        }

        const uint32_t stb = sb + (uint32_t)(kc2 % 3) * STG;

        #pragma unroll
        for (int sub = 0; sub < 2; sub++) {
            const uint32_t sbb = stb + (uint32_t)sub * SUB;
            #pragma unroll
            for (int ks = 0; ks < 2; ks++) {
                const uint32_t ca = (((uint32_t)(2 * ks) + hA) ^ sA) * 16;
                const uint32_t cb = (((uint32_t)(2 * ks) + hB) ^ sB) * 16;
                uint32_t a0[4], a1[4];
                LDSM4(a0, sbb + OFF_A + rowA + ca);
                LDSM4(a1, sbb + OFF_A + rowA + 1024 + ca);

                #pragma unroll
                for (int pp = 0; pp < 4; pp++) {
                    const uint32_t rb = rowB + (uint32_t)pp * 1024;
                    uint32_t bw[4];
                    LDSM4(bw, sbb + OFF_W + rb + cb);
                    MMA(acc[0][2 * pp],     a0, (bw + 0));
                    MMA(acc[1][2 * pp],     a1, (bw + 0));
                    MMA(acc[0][2 * pp + 1], a0, (bw + 2));
                    MMA(acc[1][2 * pp + 1], a1, (bw + 2));
                }
            }
        }
    }

    // ---- epilogue: bias + scatter by token ----
    const int gid = lane >> 2, tig = lane & 3;
    const int ncol0 = nt * 128 + n0 + 2 * tig;
    float2 bv[8];
    #pragma unroll
    for (int nb = 0; nb < 8; nb++)
        bv[nb] = *(const float2*)(bias + e * D_ + ncol0 + nb * 8);

    #pragma unroll
    for (int mf = 0; mf < 2; mf++) {
        #pragma unroll
        for (int h = 0; h < 2; h++) {
            int m = m0 + mf * 16 + h * 8 + gid;
            int tok = rows[m];
            if (tok < 0) continue;
            float* orow = out + (size_t)tok * D_ + ncol0;
            #pragma unroll
            for (int nb = 0; nb < 8; nb++) {
                float2 o;
                o.x = acc[mf][nb][2 * h]     + bv[nb].x;
                o.y = acc[mf][nb][2 * h + 1] + bv[nb].y;
                *(float2*)(orow + nb * 8) = o;
            }
        }
    }
}

// ---------------- launch ----------------
extern "C" void kernel_launch(void* const* d_in, const int* in_sizes, int n_in,
                              void* d_out, int out_size) {
    const float* x = (const float*)d_in[0];
    const int*   p = (const int*)d_in[1];
    const float* W = (const float*)d_in[2];
    const float* b = (const float*)d_in[3];
    float* out = (float*)d_out;
    const int T = in_sizes[1];

    static bool attr_done = false;
    if (!attr_done) {
        cudaFuncSetAttribute(k_gemm, cudaFuncAttributeMaxDynamicSharedMemorySize, SMEM_GEMM);
        attr_done = true;
    }

    k_zero<<<1, 32>>>();
    // 128 scatter+copy blocks + 512 W-conv blocks
    k_prep2<<<SCAT_BLK + (E_ * D_ * D_ / 8) / 512, 512>>>(p, T, x, W);

    dim3 grid(4, MAXTILES, 1);
    k_gemm<<<grid, 256, SMEM_GEMM>>>(b, out);
}

// round 17
// speedup vs baseline: 1.3296x; 1.3296x over previous
#include <cuda_runtime.h>
#include <cuda_fp16.h>
#include <cstdint>

#define E_      8
#define D_      512
#define TMAX    32768
#define MAXTILES 264

// ---------------- scratch (allocation-free __device__ globals) ----------------
__device__ int g_cursor[E_];         // invariant: all-zero at kernel_launch entry
__device__ int g_fin;                // gemm finish counter (returns to 0 each call)
__device__ int g_bucket[E_ * TMAX];

__device__ __align__(16) __half g_Xg[(size_t)TMAX * D_];   // bucket-ordered, compact
__device__ __align__(16) __half g_Wh[(size_t)E_ * D_ * D_];

// ---------------- helpers ----------------
__device__ __forceinline__ uint32_t smem_u32(const void* p) {
    uint32_t a;
    asm("{ .reg .u64 t; cvta.to.shared.u64 t, %1; cvt.u32.u64 %0, t; }" : "=r"(a) : "l"(p));
    return a;
}

#define CP16(d, s) asm volatile("cp.async.cg.shared.global [%0], [%1], 16;" :: "r"(d), "l"(s) : "memory")

#define LDSM4(r, a)                                                                  \
    asm volatile("ldmatrix.sync.aligned.m8n8.x4.shared.b16 {%0,%1,%2,%3}, [%4];"     \
        : "=r"((r)[0]), "=r"((r)[1]), "=r"((r)[2]), "=r"((r)[3]) : "r"(a))

#define MMA(c, a, b)                                                                 \
    asm volatile("mma.sync.aligned.m16n8k16.row.col.f32.f16.f16.f32 "                \
        "{%0,%1,%2,%3},{%4,%5,%6,%7},{%8,%9},{%0,%1,%2,%3};"                         \
        : "+f"((c)[0]), "+f"((c)[1]), "+f"((c)[2]), "+f"((c)[3])                     \
        : "r"((a)[0]), "r"((a)[1]), "r"((a)[2]), "r"((a)[3]),                        \
          "r"((b)[0]), "r"((b)[1]))

// ---------------- scatter only: 64 blocks x 512 threads ----------------
__global__ void __launch_bounds__(512)
k_scat(const int* __restrict__ p, int T) {
    __shared__ int s_cnt[E_], s_base[E_];
    if (threadIdx.x < E_) s_cnt[threadIdx.x] = 0;
    __syncthreads();
    int t = blockIdx.x * 512 + threadIdx.x;
    int e = 0, rank = 0;
    if (t < T) { e = p[t]; rank = atomicAdd(&s_cnt[e], 1); }
    __syncthreads();
    if (threadIdx.x < E_ && s_cnt[threadIdx.x])
        s_base[threadIdx.x] = atomicAdd(&g_cursor[threadIdx.x], s_cnt[threadIdx.x]);
    __syncthreads();
    if (t < T) g_bucket[e * TMAX + s_base[e] + rank] = t;
}

// ---------------- fused: x gather (blocks 0..2047) + W conv (2048..2559) -----
#define GATH_BLK 2048
__global__ void __launch_bounds__(512)
k_gc(const float* __restrict__ x, const float* __restrict__ W) {
    const int tid = threadIdx.x;
    if (blockIdx.x < GATH_BLK) {
        __shared__ int s_base[E_];
        if (tid == 0) {
            int a = 0;
            #pragma unroll
            for (int k = 0; k < E_; k++) { s_base[k] = a; a += g_cursor[k]; }
        }
        __syncthreads();
        const int g = blockIdx.x * 16 + (tid >> 5);
        const int lane = tid & 31;
        int e = E_ - 1;
        #pragma unroll
        for (int k = E_ - 1; k > 0; k--) if (g < s_base[k]) e = k - 1;
        const int tok = g_bucket[e * TMAX + (g - s_base[e])];

        const float4* s = (const float4*)(x + (size_t)tok * D_) + lane * 4;
        float4 v0 = s[0], v1 = s[1], v2 = s[2], v3 = s[3];
        __half2 h0 = __floats2half2_rn(v0.x, v0.y), h1 = __floats2half2_rn(v0.z, v0.w);
        __half2 h2 = __floats2half2_rn(v1.x, v1.y), h3 = __floats2half2_rn(v1.z, v1.w);
        __half2 h4 = __floats2half2_rn(v2.x, v2.y), h5 = __floats2half2_rn(v2.z, v2.w);
        __half2 h6 = __floats2half2_rn(v3.x, v3.y), h7 = __floats2half2_rn(v3.z, v3.w);
        uint4* d = (uint4*)(g_Xg + (size_t)g * D_) + lane * 2;
        d[0] = make_uint4(*(uint32_t*)&h0, *(uint32_t*)&h1, *(uint32_t*)&h2, *(uint32_t*)&h3);
        d[1] = make_uint4(*(uint32_t*)&h4, *(uint32_t*)&h5, *(uint32_t*)&h6, *(uint32_t*)&h7);
    } else {
        size_t i = (size_t)(blockIdx.x - GATH_BLK) * 512 + tid;   // per 8 floats
        float4 v0 = ((const float4*)W)[2 * i];
        float4 v1 = ((const float4*)W)[2 * i + 1];
        __half2 h0 = __floats2half2_rn(v0.x, v0.y);
        __half2 h1 = __floats2half2_rn(v0.z, v0.w);
        __half2 h2 = __floats2half2_rn(v1.x, v1.y);
        __half2 h3 = __floats2half2_rn(v1.z, v1.w);
        uint4 o;
        o.x = *(uint32_t*)&h0; o.y = *(uint32_t*)&h1;
        o.z = *(uint32_t*)&h2; o.w = *(uint32_t*)&h3;
        ((uint4*)g_Wh)[i] = o;
    }
}

// ---------------- grouped GEMM: FP16 HMMA, K-slab 64, 3-stage (r13) ----------------
// CTA 128(M) x 128(N), 8 warps, warp tile 32x64. K=512 in 8 slabs of 64.
// Stage = 2 sub-chunks of 32: [A0 A1 | W0 W1], each sub 128 rows x 64B,
// XOR swizzle c' = c ^ ((row>>1)&3). Last finished block zeroes g_cursor.
#define OFF_A       0
#define OFF_W       16384
#define SUB         8192
#define STG         32768
#define NST         3
#define SMEM_GEMM   (1024 + NST * STG)
#define NBLK        (4 * MAXTILES)

__global__ void __launch_bounds__(256, 2)
k_gemm(const float* __restrict__ bias, float* __restrict__ out) {
    extern __shared__ unsigned char smem[];
    const int tid = threadIdx.x, lane = tid & 31, wid = tid >> 5;

    // ---- inline tile list ----
    int* rows = (int*)smem;
    __shared__ int s_e, s_m, s_cnt, s_cb;
    int dep = 1;                       // data-dependency carrier for finish-add
    if (tid == 0) {
        int ti = blockIdx.y;
        int ee = -1, mm = 0, cc = 0, cb = 0, acc = 0;
        #pragma unroll
        for (int k = 0; k < E_; k++) {
            int c = g_cursor[k];
            int mt = (c + 127) >> 7;
            if (ee < 0) {
                if (ti < mt) { ee = k; mm = ti; cc = c; cb = acc; }
                else ti -= mt;
            }
            acc += c;
        }
        s_e = ee; s_m = mm; s_cnt = cc; s_cb = cb;
        asm volatile("" : "+r"(dep) : "r"(acc));   // order finish-add after loads
    }
    __syncthreads();
    const int e = s_e;

    if (e >= 0) {
        const int nt = blockIdx.x, mtile = s_m, count = s_cnt, cbase = s_cb;

        if (tid < 128) {
            int m = mtile * 128 + tid;
            rows[tid] = (m < count) ? g_bucket[e * TMAX + m] : -1;
        }
        __syncthreads();

        // ---- loader: row = tid>>1, 32B half = tid&1; A sequential ----
        const int lrow = tid >> 1;
        const int hh = tid & 1;
        const int am = mtile * 128 + lrow;
        const int arow = (am < count) ? (cbase + am) : cbase;
        const char* srcA = (const char*)(g_Xg + (size_t)arow * D_) + hh * 32;
        const char* srcW = (const char*)(g_Wh
                            + ((size_t)e * D_ + (size_t)(nt * 128 + lrow)) * D_) + hh * 32;

        const uint32_t sb = smem_u32(smem) + 1024;
        const uint32_t c0 = (uint32_t)hh * 2;
        const uint32_t sw_ = (uint32_t)((lrow >> 1) & 3);
        const uint32_t d0 = (uint32_t)lrow * 64 + ((c0 ^ sw_) * 16);
        const uint32_t d1 = (uint32_t)lrow * 64 + (((c0 + 1) ^ sw_) * 16);

        #define LOAD_STAGE(st, kc2) do {                                             \
            uint32_t b_ = sb + (uint32_t)(st) * STG;                                  \
            const char* sa_ = srcA + (size_t)(kc2) * 128;                             \
            const char* sw2_ = srcW + (size_t)(kc2) * 128;                            \
            CP16(b_ + OFF_A + d0,       sa_);       CP16(b_ + OFF_A + d1,       sa_ + 16);\
            CP16(b_ + OFF_A + SUB + d0, sa_ + 64);  CP16(b_ + OFF_A + SUB + d1, sa_ + 80);\
            CP16(b_ + OFF_W + d0,       sw2_);      CP16(b_ + OFF_W + d1,       sw2_ + 16);\
            CP16(b_ + OFF_W + SUB + d0, sw2_ + 64); CP16(b_ + OFF_W + SUB + d1, sw2_ + 80);\
            asm volatile("cp.async.commit_group;" ::: "memory");                      \
        } while (0)

        // ---- mma fragment addressing: warp tile 32x64 ----
        const int m0 = (wid & 3) * 32;
        const int n0 = (wid >> 2) * 64;
        const uint32_t rA  = (uint32_t)(m0 + (lane & 15));
        const uint32_t hA  = (uint32_t)((lane >> 4) & 1);
        const uint32_t sA  = (rA >> 1) & 3;
        const uint32_t rowA = rA * 64;
        const uint32_t rB0 = (uint32_t)(n0 + ((lane >> 4) & 1) * 8 + (lane & 7));
        const uint32_t hB  = (uint32_t)((lane >> 3) & 1);
        const uint32_t sB  = (rB0 >> 1) & 3;
        const uint32_t rowB = rB0 * 64;

        float acc[2][8][4];
        #pragma unroll
        for (int i = 0; i < 2; i++)
            #pragma unroll
            for (int j = 0; j < 8; j++)
                #pragma unroll
                for (int q = 0; q < 4; q++) acc[i][j][q] = 0.f;

        LOAD_STAGE(0, 0);
        LOAD_STAGE(1, 1);

        for (int kc2 = 0; kc2 < 8; kc2++) {
            if (kc2 < 6) asm volatile("cp.async.wait_group 1;" ::: "memory");
            else         asm volatile("cp.async.wait_group 0;" ::: "memory");
            __syncthreads();
            if (kc2 + 2 < 8) LOAD_STAGE((kc2 + 2) % 3, kc2 + 2);

            const uint32_t stb = sb + (uint32_t)(kc2 % 3) * STG;

            #pragma unroll
            for (int sub = 0; sub < 2; sub++) {
                const uint32_t sbb = stb + (uint32_t)sub * SUB;
                #pragma unroll
                for (int ks = 0; ks < 2; ks++) {
                    const uint32_t ca = (((uint32_t)(2 * ks) + hA) ^ sA) * 16;
                    const uint32_t cb = (((uint32_t)(2 * ks) + hB) ^ sB) * 16;
                    uint32_t a0[4], a1[4];
                    LDSM4(a0, sbb + OFF_A + rowA + ca);
                    LDSM4(a1, sbb + OFF_A + rowA + 1024 + ca);

                    #pragma unroll
                    for (int pp = 0; pp < 4; pp++) {
                        const uint32_t rb = rowB + (uint32_t)pp * 1024;
                        uint32_t bw[4];
                        LDSM4(bw, sbb + OFF_W + rb + cb);
                        MMA(acc[0][2 * pp],     a0, (bw + 0));
                        MMA(acc[1][2 * pp],     a1, (bw + 0));
                        MMA(acc[0][2 * pp + 1], a0, (bw + 2));
                        MMA(acc[1][2 * pp + 1], a1, (bw + 2));
                    }
                }
            }
        }

        // ---- epilogue: bias + scatter by token ----
        const int gid = lane >> 2, tig = lane & 3;
        const int ncol0 = nt * 128 + n0 + 2 * tig;
        float2 bv[8];
        #pragma unroll
        for (int nb = 0; nb < 8; nb++)
            bv[nb] = *(const float2*)(bias + e * D_ + ncol0 + nb * 8);

        #pragma unroll
        for (int mf = 0; mf < 2; mf++) {
            #pragma unroll
            for (int h = 0; h < 2; h++) {
                int m = m0 + mf * 16 + h * 8 + gid;
                int tok = rows[m];
                if (tok < 0) continue;
                float* orow = out + (size_t)tok * D_ + ncol0;
                #pragma unroll
                for (int nb = 0; nb < 8; nb++) {
                    float2 o;
                    o.x = acc[mf][nb][2 * h]     + bv[nb].x;
                    o.y = acc[mf][nb][2 * h + 1] + bv[nb].y;
                    *(float2*)(orow + nb * 8) = o;
                }
            }
        }
    }

    // ---- finish: last block restores the g_cursor == 0 invariant ----
    if (tid == 0) {
        int fin = atomicAdd(&g_fin, dep);          // dep==1, ordered after cursor reads
        if (fin == NBLK - 1) {
            #pragma unroll
            for (int k = 0; k < E_; k++) g_cursor[k] = 0;
            g_fin = 0;
        }
    }
}

// ---------------- launch ----------------
extern "C" void kernel_launch(void* const* d_in, const int* in_sizes, int n_in,
                              void* d_out, int out_size) {
    const float* x = (const float*)d_in[0];
    const int*   p = (const int*)d_in[1];
    const float* W = (const float*)d_in[2];
    const float* b = (const float*)d_in[3];
    float* out = (float*)d_out;
    const int T = in_sizes[1];

    static bool attr_done = false;
    if (!attr_done) {
        cudaFuncSetAttribute(k_gemm, cudaFuncAttributeMaxDynamicSharedMemorySize, SMEM_GEMM);
        attr_done = true;
    }

    k_scat<<<(T + 511) / 512, 512>>>(p, T);
    k_gc<<<GATH_BLK + (E_ * D_ * D_ / 8) / 512, 512>>>(x, W);

    dim3 grid(4, MAXTILES, 1);
    k_gemm<<<grid, 256, SMEM_GEMM>>>(b, out);
}